// round 1
// baseline (speedup 1.0000x reference)
#include <cuda_runtime.h>
#include <math.h>

// Problem constants
#define NB 4
#define NS 2048
#define ND 1024
#define NH 16
#define NHD 64

// Scratch for projected Q/K/V in [b,h,s,d] layout (32 MB each)
__device__ float g_q[(size_t)NB * NH * NS * NHD];
__device__ float g_k[(size_t)NB * NH * NS * NHD];
__device__ float g_v[(size_t)NB * NH * NS * NHD];

// ---------------------------------------------------------------------------
// Fused QKV projection: C[m, n] = sum_k x[m,k] * W[n,k] + b[n]
// M = B*S = 8192, fused N = 3*1024, K = 1024.
// Tile: 128(M) x 64(N), 256 threads, each thread 8x4 outputs, K-tile 16.
// Output scattered directly into [b,h,s,d] scratch.
// ---------------------------------------------------------------------------
__global__ __launch_bounds__(256) void qkv_gemm(
    const float* __restrict__ x,
    const float* __restrict__ Wq, const float* __restrict__ bq,
    const float* __restrict__ Wk, const float* __restrict__ bk,
    const float* __restrict__ Wv, const float* __restrict__ bv)
{
    __shared__ float xst[16][132];  // [kk][m], pad 4 -> stores 2-way, reads CF
    __shared__ float wst[16][68];   // [kk][n], pad 4 -> float4 reads CF/aligned

    const int t  = threadIdx.x;
    const int tx = t & 15;          // n group (4 cols each)
    const int ty = t >> 4;          // m group (8 rows each)
    const int m0 = blockIdx.y * 128;
    const int n0 = blockIdx.x * 64;         // fused n in [0, 3072)
    const int which = n0 >> 10;             // 0=Q, 1=K, 2=V
    const float* W    = (which == 0) ? Wq : ((which == 1) ? Wk : Wv);
    const float* bias = (which == 0) ? bq : ((which == 1) ? bk : bv);
    const int ncol0 = n0 & 1023;

    float acc[8][4];
    #pragma unroll
    for (int i = 0; i < 8; i++)
        #pragma unroll
        for (int j = 0; j < 4; j++) acc[i][j] = 0.0f;

    const int row = t >> 2;   // 0..63
    const int cg  = t & 3;    // float4 column group within k-tile

    for (int k0 = 0; k0 < 1024; k0 += 16) {
        // Load x tile 128x16 (two passes of 64 rows), transpose into smem
        #pragma unroll
        for (int p = 0; p < 2; p++) {
            const int m = row + p * 64;
            float4 v = *(const float4*)&x[(size_t)(m0 + m) * 1024 + k0 + cg * 4];
            xst[cg * 4 + 0][m] = v.x;
            xst[cg * 4 + 1][m] = v.y;
            xst[cg * 4 + 2][m] = v.z;
            xst[cg * 4 + 3][m] = v.w;
        }
        // Load W tile 64x16, transpose into smem
        {
            float4 wv = *(const float4*)&W[(size_t)(ncol0 + row) * 1024 + k0 + cg * 4];
            wst[cg * 4 + 0][row] = wv.x;
            wst[cg * 4 + 1][row] = wv.y;
            wst[cg * 4 + 2][row] = wv.z;
            wst[cg * 4 + 3][row] = wv.w;
        }
        __syncthreads();

        #pragma unroll
        for (int kk = 0; kk < 16; kk++) {
            float a[8];
            #pragma unroll
            for (int i = 0; i < 8; i++) a[i] = xst[kk][ty * 8 + i];
            float4 b4 = *(const float4*)&wst[kk][tx * 4];
            float b[4] = {b4.x, b4.y, b4.z, b4.w};
            #pragma unroll
            for (int i = 0; i < 8; i++)
                #pragma unroll
                for (int j = 0; j < 4; j++)
                    acc[i][j] += a[i] * b[j];
        }
        __syncthreads();
    }

    // Epilogue: bias + scatter into [b,h,s,d]
    float* dst = (which == 0) ? g_q : ((which == 1) ? g_k : g_v);
    #pragma unroll
    for (int j = 0; j < 4; j++) {
        const int ncol = ncol0 + tx * 4 + j;
        const float bb = bias[ncol];
        const int h  = ncol >> 6;
        const int hd = ncol & 63;
        #pragma unroll
        for (int i = 0; i < 8; i++) {
            const int m  = m0 + ty * 8 + i;
            const int b_ = m >> 11;     // / 2048
            const int s  = m & 2047;
            dst[(((size_t)(b_ * NH + h)) * NS + s) * NHD + hd] = acc[i][j] + bb;
        }
    }
}

// ---------------------------------------------------------------------------
// Flash attention: one CTA handles one (b,h) x 64-row Q block.
// Streams 64-key tiles with online softmax. fp32 throughout.
// ---------------------------------------------------------------------------
__global__ __launch_bounds__(256) void attn_kernel(float* __restrict__ out)
{
    extern __shared__ float sm[];
    float* qst = sm;                 // [64][64]  d-major: qst[d*64 + q]   (reads CF broadcast)
    float* kst = qst + 64 * 64;      // [64][68]  d-major: kst[d*68 + n]   (float4 reads CF)
    float* vs  = kst + 64 * 68;      // [64][64]  k-major: vs[k*64 + d]    (float4 reads CF)
    float* pst = vs  + 64 * 64;      // [64][65]  k-major: pst[k*65 + q]   (pad -> CF both ways)

    const int t  = threadIdx.x;
    const int tx = t & 15;           // n (keys) or d (output) group, 4 each
    const int ty = t >> 4;           // q group, 4 each
    const int qb = blockIdx.x;       // 0..31
    const int bh = blockIdx.y;       // 0..63 = b*16 + h
    const size_t base = (size_t)bh * NS * NHD;
    const int q0 = qb * 64;

    // Load Q tile [64 x 64], transposed into qst[d][q]
    #pragma unroll
    for (int p = 0; p < 4; p++) {
        const int idx = p * 256 + t;      // 0..1023 float4s
        const int r = idx >> 4;           // q row
        const int c = idx & 15;           // float4 col group
        float4 v = *(const float4*)&g_q[base + (size_t)(q0 + r) * 64 + c * 4];
        qst[(c * 4 + 0) * 64 + r] = v.x;
        qst[(c * 4 + 1) * 64 + r] = v.y;
        qst[(c * 4 + 2) * 64 + r] = v.z;
        qst[(c * 4 + 3) * 64 + r] = v.w;
    }

    float oacc[4][4];
    float mrow[4], lrow[4];
    #pragma unroll
    for (int i = 0; i < 4; i++) {
        mrow[i] = -1e30f;
        lrow[i] = 0.0f;
        #pragma unroll
        for (int j = 0; j < 4; j++) oacc[i][j] = 0.0f;
    }

    const float scale = 0.125f;  // 1/sqrt(64)

    for (int n0 = 0; n0 < NS; n0 += 64) {
        __syncthreads();  // prior-iter readers of kst/vs/pst done; also covers qst store on iter 0

        // Load K tile transposed into kst[d][n], V tile straight into vs[k][d]
        #pragma unroll
        for (int p = 0; p < 4; p++) {
            const int idx = p * 256 + t;
            const int r = idx >> 4;
            const int c = idx & 15;
            float4 kv = *(const float4*)&g_k[base + (size_t)(n0 + r) * 64 + c * 4];
            kst[(c * 4 + 0) * 68 + r] = kv.x;
            kst[(c * 4 + 1) * 68 + r] = kv.y;
            kst[(c * 4 + 2) * 68 + r] = kv.z;
            kst[(c * 4 + 3) * 68 + r] = kv.w;
            float4 vv = *(const float4*)&g_v[base + (size_t)(n0 + r) * 64 + c * 4];
            *(float4*)&vs[r * 64 + c * 4] = vv;
        }
        __syncthreads();

        // S = Q K^T  (4x4 fragment per thread)
        float s[4][4];
        #pragma unroll
        for (int i = 0; i < 4; i++)
            #pragma unroll
            for (int j = 0; j < 4; j++) s[i][j] = 0.0f;

        #pragma unroll 8
        for (int d = 0; d < 64; d++) {
            float a[4];
            #pragma unroll
            for (int i = 0; i < 4; i++) a[i] = qst[d * 64 + ty * 4 + i];
            float4 b4 = *(const float4*)&kst[d * 68 + tx * 4];
            float b[4] = {b4.x, b4.y, b4.z, b4.w};
            #pragma unroll
            for (int i = 0; i < 4; i++)
                #pragma unroll
                for (int j = 0; j < 4; j++)
                    s[i][j] += a[i] * b[j];
        }

        // Online softmax update; write P transposed to pst[k][q]
        #pragma unroll
        for (int i = 0; i < 4; i++) {
            float s0 = s[i][0] * scale;
            float s1 = s[i][1] * scale;
            float s2 = s[i][2] * scale;
            float s3 = s[i][3] * scale;
            float rm = fmaxf(fmaxf(s0, s1), fmaxf(s2, s3));
            #pragma unroll
            for (int msk = 1; msk < 16; msk <<= 1)
                rm = fmaxf(rm, __shfl_xor_sync(0xffffffffu, rm, msk));
            const float mnew = fmaxf(mrow[i], rm);
            const float alpha = __expf(mrow[i] - mnew);
            mrow[i] = mnew;

            float p0 = __expf(s0 - mnew);
            float p1 = __expf(s1 - mnew);
            float p2 = __expf(s2 - mnew);
            float p3 = __expf(s3 - mnew);
            pst[(tx * 4 + 0) * 65 + ty * 4 + i] = p0;
            pst[(tx * 4 + 1) * 65 + ty * 4 + i] = p1;
            pst[(tx * 4 + 2) * 65 + ty * 4 + i] = p2;
            pst[(tx * 4 + 3) * 65 + ty * 4 + i] = p3;
            float rs = p0 + p1 + p2 + p3;
            #pragma unroll
            for (int msk = 1; msk < 16; msk <<= 1)
                rs += __shfl_xor_sync(0xffffffffu, rs, msk);
            lrow[i] = lrow[i] * alpha + rs;
            #pragma unroll
            for (int j = 0; j < 4; j++) oacc[i][j] *= alpha;
        }
        __syncthreads();

        // O += P V
        #pragma unroll 8
        for (int k = 0; k < 64; k++) {
            float a[4];
            #pragma unroll
            for (int i = 0; i < 4; i++) a[i] = pst[k * 65 + ty * 4 + i];
            float4 b4 = *(const float4*)&vs[k * 64 + tx * 4];
            float b[4] = {b4.x, b4.y, b4.z, b4.w};
            #pragma unroll
            for (int i = 0; i < 4; i++)
                #pragma unroll
                for (int j = 0; j < 4; j++)
                    oacc[i][j] += a[i] * b[j];
        }
    }

    // Epilogue: normalize and write out[b, s, h*64 + d]
    const int b_ = bh >> 4;
    const int h  = bh & 15;
    #pragma unroll
    for (int i = 0; i < 4; i++) {
        const int qrow = q0 + ty * 4 + i;
        const float inv = 1.0f / lrow[i];
        #pragma unroll
        for (int j = 0; j < 4; j++) {
            out[((size_t)(b_ * NS + qrow)) * ND + h * 64 + tx * 4 + j] = oacc[i][j] * inv;
        }
    }
}

// ---------------------------------------------------------------------------
extern "C" void kernel_launch(void* const* d_in, const int* in_sizes, int n_in,
                              void* d_out, int out_size)
{
    const float* x  = (const float*)d_in[0];
    const float* Wq = (const float*)d_in[1];
    const float* bq = (const float*)d_in[2];
    const float* Wk = (const float*)d_in[3];
    const float* bk = (const float*)d_in[4];
    const float* Wv = (const float*)d_in[5];
    const float* bv = (const float*)d_in[6];
    float* out = (float*)d_out;

    // QKV projection: grid (48 n-tiles, 64 m-tiles)
    dim3 g1(48, 64);
    qkv_gemm<<<g1, 256>>>(x, Wq, bq, Wk, bk, Wv, bv);

    // Attention: grid (32 q-blocks, 64 bh pairs)
    const size_t smem = (size_t)(64 * 64 + 64 * 68 + 64 * 64 + 64 * 65) * sizeof(float);
    cudaFuncSetAttribute(attn_kernel, cudaFuncAttributeMaxDynamicSharedMemorySize, (int)smem);
    dim3 g2(32, 64);
    attn_kernel<<<g2, 256, smem>>>(out);
}